// round 1
// baseline (speedup 1.0000x reference)
#include <cuda_runtime.h>

// Problem constants (fixed by the dataset):
//   B=8, MSP=2048, D=512, A=64, NB=5
// Inputs (metadata order): e_output [8*2048*512] f32, W_ll [64*2048] f32,
//   b_ll [64] f32, W_fl [5*1024] f32, b_fl [5] f32, (max_atoms scalar, unused)
// Output: [8,64,64,5] f32 = 163840 elements.
//
// Algorithm (contraction reordering, exact in infinite precision):
//   Wc[n,d]   = W_fl[n,d] + W_fl[n,512+d]
//   S[n]      = sum_d Wc[n,d]
//   t[b,s,n]  = sum_d e[b,s,d] * Wc[n,d]
//   out[b,a,n]= sum_s W_ll[a,s] * t[b,s,n] + b_ll[a]*S[n] + b_fl[n]
//   final[b,i,j,n] = out[b,i,n]   (broadcast over j)

#define NROWS  16384      // B * MSP
#define DVAL   512
#define NB     5
#define AVAL   64
#define BVAL   8
#define MSP    2048

// Scratch (allocation-free rule: __device__ globals)
__device__ float g_Wc[NB * DVAL];          // 2560 floats
__device__ float g_S[NB];
__device__ float g_t[NROWS * NB];          // 81920 floats (320 KB)

// ---------------------------------------------------------------------------
// Kernel 1: Wc and S.  grid = NB blocks, 256 threads.
// ---------------------------------------------------------------------------
__global__ void prep_kernel(const float* __restrict__ W_fl) {
    const int n   = blockIdx.x;
    const int tid = threadIdx.x;
    __shared__ float red[256];

    float s = 0.f;
    for (int d = tid; d < DVAL; d += 256) {
        float v = W_fl[n * 1024 + d] + W_fl[n * 1024 + 512 + d];
        g_Wc[n * DVAL + d] = v;
        s += v;
    }
    red[tid] = s;
    __syncthreads();
    #pragma unroll
    for (int st = 128; st > 0; st >>= 1) {
        if (tid < st) red[tid] += red[tid + st];
        __syncthreads();
    }
    if (tid == 0) g_S[n] = red[0];
}

// ---------------------------------------------------------------------------
// Kernel 2: t[b,s,n] = <e_row, Wc[n]>.  One warp per row (grid-stride).
// Wc kept in 80 registers per thread (staged through smem once per block).
// 256 threads/block, 2 blocks/SM target.
// ---------------------------------------------------------------------------
__global__ __launch_bounds__(256) void t_kernel(const float* __restrict__ e) {
    __shared__ float wcs[NB * DVAL];   // 10 KB
    const int tid  = threadIdx.x;
    const int lane = tid & 31;
    const int warp = tid >> 5;

    // Cooperative stage of Wc into smem (single coalesced pass from L2)
    for (int i = tid; i < NB * DVAL; i += 256) wcs[i] = g_Wc[i];
    __syncthreads();

    // Per-lane register copy: lane handles d = r*128 + lane*4 .. +3, r=0..3
    float4 wc[4][NB];
    #pragma unroll
    for (int r = 0; r < 4; r++)
        #pragma unroll
        for (int n = 0; n < NB; n++)
            wc[r][n] = *(const float4*)&wcs[n * DVAL + r * 128 + lane * 4];

    const int gw = blockIdx.x * 8 + warp;
    const int nw = gridDim.x * 8;

    for (int row = gw; row < NROWS; row += nw) {
        const float4* er = (const float4*)(e + (size_t)row * DVAL);

        // Front-batched loads: MLP = 4 LDG.128 per warp
        float4 ev[4];
        #pragma unroll
        for (int r = 0; r < 4; r++) ev[r] = er[r * 32 + lane];

        float acc[NB];
        #pragma unroll
        for (int n = 0; n < NB; n++) acc[n] = 0.f;

        #pragma unroll
        for (int r = 0; r < 4; r++) {
            #pragma unroll
            for (int n = 0; n < NB; n++) {
                acc[n] += ev[r].x * wc[r][n].x;
                acc[n] += ev[r].y * wc[r][n].y;
                acc[n] += ev[r].z * wc[r][n].z;
                acc[n] += ev[r].w * wc[r][n].w;
            }
        }

        // Butterfly reduce each of the 5 partial sums across the warp
        #pragma unroll
        for (int n = 0; n < NB; n++) {
            #pragma unroll
            for (int off = 16; off > 0; off >>= 1)
                acc[n] += __shfl_xor_sync(0xFFFFFFFFu, acc[n], off);
        }

        if (lane == 0) {
            float* tp = &g_t[row * NB];
            #pragma unroll
            for (int n = 0; n < NB; n++) tp[n] = acc[n];
        }
    }
}

// ---------------------------------------------------------------------------
// Kernel 3: out[b,a,n] + broadcast over j.
// grid = (4 a-tiles, 8 batches), 512 threads (16 warps, one warp per a).
// t[b] staged in 40 KB smem; stride-5 LDS is conflict-free (5 coprime 32).
// ---------------------------------------------------------------------------
__global__ __launch_bounds__(512) void out_kernel(const float* __restrict__ W_ll,
                                                  const float* __restrict__ b_ll,
                                                  const float* __restrict__ b_fl,
                                                  float* __restrict__ out) {
    __shared__ float ts[MSP * NB];     // 40 KB
    const int b   = blockIdx.y;
    const int at  = blockIdx.x;
    const int tid = threadIdx.x;

    for (int i = tid; i < MSP * NB; i += 512) ts[i] = g_t[b * (MSP * NB) + i];
    __syncthreads();

    const int lane = tid & 31;
    const int w    = tid >> 5;
    const int a    = at * 16 + w;
    const float* wrow = W_ll + (size_t)a * MSP;

    float a0 = 0.f, a1 = 0.f, a2 = 0.f, a3 = 0.f, a4 = 0.f;
    #pragma unroll 4
    for (int s = lane; s < MSP; s += 32) {
        float wv = wrow[s];
        const float* tp = &ts[s * NB];
        a0 += wv * tp[0];
        a1 += wv * tp[1];
        a2 += wv * tp[2];
        a3 += wv * tp[3];
        a4 += wv * tp[4];
    }
    #pragma unroll
    for (int off = 16; off > 0; off >>= 1) {
        a0 += __shfl_xor_sync(0xFFFFFFFFu, a0, off);
        a1 += __shfl_xor_sync(0xFFFFFFFFu, a1, off);
        a2 += __shfl_xor_sync(0xFFFFFFFFu, a2, off);
        a3 += __shfl_xor_sync(0xFFFFFFFFu, a3, off);
        a4 += __shfl_xor_sync(0xFFFFFFFFu, a4, off);
    }

    const float bl = b_ll[a];
    a0 += bl * g_S[0] + b_fl[0];
    a1 += bl * g_S[1] + b_fl[1];
    a2 += bl * g_S[2] + b_fl[2];
    a3 += bl * g_S[3] + b_fl[3];
    a4 += bl * g_S[4] + b_fl[4];

    // Broadcast over j: 64 * 5 = 320 floats per (b,a)
    float* base = out + ((size_t)(b * AVAL + a)) * (AVAL * NB);
    for (int idx = lane; idx < AVAL * NB; idx += 32) {
        int n = idx % NB;
        float v = (n == 0) ? a0 : (n == 1) ? a1 : (n == 2) ? a2 : (n == 3) ? a3 : a4;
        base[idx] = v;
    }
}

// ---------------------------------------------------------------------------
extern "C" void kernel_launch(void* const* d_in, const int* in_sizes, int n_in,
                              void* d_out, int out_size) {
    const float* e    = (const float*)d_in[0];   // [8,2048,512]
    const float* W_ll = (const float*)d_in[1];   // [64,2048]
    const float* b_ll = (const float*)d_in[2];   // [64]
    const float* W_fl = (const float*)d_in[3];   // [5,1024]
    const float* b_fl = (const float*)d_in[4];   // [5]
    float* out = (float*)d_out;                  // [8,64,64,5]

    prep_kernel<<<NB, 256>>>(W_fl);
    t_kernel<<<296, 256>>>(e);
    out_kernel<<<dim3(4, BVAL), 512>>>(W_ll, b_ll, b_fl, out);
}

// round 2
// speedup vs baseline: 1.1573x; 1.1573x over previous
#include <cuda_runtime.h>

// B=8, MSP=2048, D=512, A=64, NB=5
// Inputs: e_output [8*2048*512] f32, W_ll [64*2048] f32, b_ll [64] f32,
//         W_fl [5*1024] f32, b_fl [5] f32, (max_atoms scalar unused)
// Output: [8,64,64,5] f32.
//
// Algorithm (exact contraction reordering):
//   Wc[n,d]   = W_fl[n,d] + W_fl[n,512+d]
//   S[n]      = sum_d Wc[n,d]
//   t[b,s,n]  = sum_d e[b,s,d] * Wc[n,d]
//   out[b,a,n]= sum_s W_ll[a,s] * t[b,s,n] + b_ll[a]*S[n] + b_fl[n]
//   final[b,i,j,n] = out[b,i,n]

#define NROWS  16384      // B * MSP
#define DVAL   512
#define NB     5
#define AVAL   64
#define BVAL   8
#define MSP    2048

__device__ float g_S[NB];
__device__ float g_t[NROWS * NB];          // 320 KB scratch

// ---------------------------------------------------------------------------
// Kernel 1: t[b,s,n] = <e_row, Wc[n]>.  One warp per row (grid-stride).
// Wc built per-block from W_fl (10 KB from L2), then held in 80 regs/thread.
// Block 0 warp 0 additionally computes S.
// ---------------------------------------------------------------------------
__global__ __launch_bounds__(256, 2) void t_kernel(const float* __restrict__ e,
                                                   const float* __restrict__ W_fl) {
    __shared__ float wcs[NB * DVAL];   // 10 KB
    const int tid  = threadIdx.x;
    const int lane = tid & 31;
    const int warp = tid >> 5;

    // Build Wc in smem: Wc[n][d] = W_fl[n][d] + W_fl[n][512+d]
    for (int i = tid; i < NB * DVAL; i += 256) {
        int n = i / DVAL, d = i - n * DVAL;
        wcs[i] = W_fl[n * 1024 + d] + W_fl[n * 1024 + 512 + d];
    }
    __syncthreads();

    // Block 0, warp 0: compute S[n] = sum_d Wc[n][d]
    if (blockIdx.x == 0 && warp == 0) {
        #pragma unroll
        for (int n = 0; n < NB; n++) {
            float s = 0.f;
            for (int d = lane; d < DVAL; d += 32) s += wcs[n * DVAL + d];
            #pragma unroll
            for (int off = 16; off > 0; off >>= 1)
                s += __shfl_xor_sync(0xFFFFFFFFu, s, off);
            if (lane == 0) g_S[n] = s;
        }
    }

    // Per-lane register copy of Wc: lane handles d = r*128 + lane*4 .. +3
    float4 wc[4][NB];
    #pragma unroll
    for (int r = 0; r < 4; r++)
        #pragma unroll
        for (int n = 0; n < NB; n++)
            wc[r][n] = *(const float4*)&wcs[n * DVAL + r * 128 + lane * 4];

    const int gw = blockIdx.x * 8 + warp;
    const int nw = gridDim.x * 8;

    for (int row = gw; row < NROWS; row += nw) {
        const float4* er = (const float4*)(e + (size_t)row * DVAL);

        // Front-batched loads: MLP = 4 LDG.128 per lane
        float4 ev[4];
        #pragma unroll
        for (int r = 0; r < 4; r++) ev[r] = er[r * 32 + lane];

        float acc[NB];
        #pragma unroll
        for (int n = 0; n < NB; n++) acc[n] = 0.f;

        #pragma unroll
        for (int r = 0; r < 4; r++) {
            #pragma unroll
            for (int n = 0; n < NB; n++) {
                acc[n] += ev[r].x * wc[r][n].x;
                acc[n] += ev[r].y * wc[r][n].y;
                acc[n] += ev[r].z * wc[r][n].z;
                acc[n] += ev[r].w * wc[r][n].w;
            }
        }

        #pragma unroll
        for (int n = 0; n < NB; n++) {
            #pragma unroll
            for (int off = 16; off > 0; off >>= 1)
                acc[n] += __shfl_xor_sync(0xFFFFFFFFu, acc[n], off);
        }

        if (lane == 0) {
            float* tp = &g_t[row * NB];
            #pragma unroll
            for (int n = 0; n < NB; n++) tp[n] = acc[n];
        }
    }
}

// ---------------------------------------------------------------------------
// Kernel 2: out[b,a,n] + broadcast over j.
// grid = (16 a-tiles, 8 batches), 128 threads (4 warps, one warp per a).
// t[b] staged in 40 KB smem; stride-5 LDS is conflict-free (5 coprime 32).
// LDS traffic: 4 warps x 40KB = 160KB/block (~1280 cyc), 128 blocks in parallel.
// ---------------------------------------------------------------------------
__global__ __launch_bounds__(128) void out_kernel(const float* __restrict__ W_ll,
                                                  const float* __restrict__ b_ll,
                                                  const float* __restrict__ b_fl,
                                                  float* __restrict__ out) {
    __shared__ float ts[MSP * NB];     // 40 KB
    const int b   = blockIdx.y;
    const int at  = blockIdx.x;
    const int tid = threadIdx.x;

    // Stage t[b] (40 KB) from L2 with float4 loads
    {
        const float4* src = (const float4*)&g_t[b * (MSP * NB)];
        float4* dst = (float4*)ts;
        for (int i = tid; i < (MSP * NB) / 4; i += 128) dst[i] = src[i];
    }
    __syncthreads();

    const int lane = tid & 31;
    const int w    = tid >> 5;
    const int a    = at * 4 + w;
    const float* wrow = W_ll + (size_t)a * MSP;

    float a0 = 0.f, a1 = 0.f, a2 = 0.f, a3 = 0.f, a4 = 0.f;
    #pragma unroll 4
    for (int s = lane; s < MSP; s += 32) {
        float wv = wrow[s];
        const float* tp = &ts[s * NB];
        a0 += wv * tp[0];
        a1 += wv * tp[1];
        a2 += wv * tp[2];
        a3 += wv * tp[3];
        a4 += wv * tp[4];
    }
    #pragma unroll
    for (int off = 16; off > 0; off >>= 1) {
        a0 += __shfl_xor_sync(0xFFFFFFFFu, a0, off);
        a1 += __shfl_xor_sync(0xFFFFFFFFu, a1, off);
        a2 += __shfl_xor_sync(0xFFFFFFFFu, a2, off);
        a3 += __shfl_xor_sync(0xFFFFFFFFu, a3, off);
        a4 += __shfl_xor_sync(0xFFFFFFFFu, a4, off);
    }

    const float bl = b_ll[a];
    a0 += bl * g_S[0] + b_fl[0];
    a1 += bl * g_S[1] + b_fl[1];
    a2 += bl * g_S[2] + b_fl[2];
    a3 += bl * g_S[3] + b_fl[3];
    a4 += bl * g_S[4] + b_fl[4];

    // Broadcast over j: 64 * 5 = 320 floats per (b,a)
    float* base = out + ((size_t)(b * AVAL + a)) * (AVAL * NB);
    for (int idx = lane; idx < AVAL * NB; idx += 32) {
        int n = idx % NB;
        float v = (n == 0) ? a0 : (n == 1) ? a1 : (n == 2) ? a2 : (n == 3) ? a3 : a4;
        base[idx] = v;
    }
}

// ---------------------------------------------------------------------------
extern "C" void kernel_launch(void* const* d_in, const int* in_sizes, int n_in,
                              void* d_out, int out_size) {
    const float* e    = (const float*)d_in[0];
    const float* W_ll = (const float*)d_in[1];
    const float* b_ll = (const float*)d_in[2];
    const float* W_fl = (const float*)d_in[3];
    const float* b_fl = (const float*)d_in[4];
    float* out = (float*)d_out;

    t_kernel<<<296, 256>>>(e, W_fl);
    out_kernel<<<dim3(16, BVAL), 128>>>(W_ll, b_ll, b_fl, out);
}

// round 3
// speedup vs baseline: 1.7083x; 1.4760x over previous
#include <cuda_runtime.h>

// B=8, MSP=2048, D=512, A=64, NB=5
// Inputs: e_output [8*2048*512] f32, W_ll [64*2048] f32, b_ll [64] f32,
//         W_fl [5*1024] f32, b_fl [5] f32, (max_atoms scalar unused)
// Output: [8,64,64,5] f32.
//
// Algorithm (exact contraction reordering):
//   Wc[n,d]   = W_fl[n,d] + W_fl[n,512+d]
//   S[n]      = sum_d Wc[n,d]
//   t[b,s,n]  = sum_d e[b,s,d] * Wc[n,d]
//   out[b,a,n]= sum_s W_ll[a,s] * t[b,s,n] + b_ll[a]*S[n] + b_fl[n]
//   final[b,i,j,n] = out[b,i,n]

#define NROWS  16384      // B * MSP
#define DVAL   512
#define NB     5
#define AVAL   64
#define BVAL   8
#define MSP    2048

__device__ float g_S[NB];
__device__ float g_t[NROWS * NB];          // 320 KB scratch (L2-resident)

// ---------------------------------------------------------------------------
// Kernel 1: t[b,s,n] = <e_row, Wc[n]>.  One warp per row (grid-stride).
// Wc built per-block from W_fl, held in 80 regs/thread. Block 0 computes S.
// L2-bandwidth-bound (e_output is L2-resident across replays).
// ---------------------------------------------------------------------------
__global__ __launch_bounds__(256, 2) void t_kernel(const float* __restrict__ e,
                                                   const float* __restrict__ W_fl) {
    __shared__ float wcs[NB * DVAL];   // 10 KB
    const int tid  = threadIdx.x;
    const int lane = tid & 31;
    const int warp = tid >> 5;

    for (int i = tid; i < NB * DVAL; i += 256) {
        int n = i / DVAL, d = i - n * DVAL;
        wcs[i] = W_fl[n * 1024 + d] + W_fl[n * 1024 + 512 + d];
    }
    __syncthreads();

    if (blockIdx.x == 0 && warp == 0) {
        #pragma unroll
        for (int n = 0; n < NB; n++) {
            float s = 0.f;
            for (int d = lane; d < DVAL; d += 32) s += wcs[n * DVAL + d];
            #pragma unroll
            for (int off = 16; off > 0; off >>= 1)
                s += __shfl_xor_sync(0xFFFFFFFFu, s, off);
            if (lane == 0) g_S[n] = s;
        }
    }

    float4 wc[4][NB];
    #pragma unroll
    for (int r = 0; r < 4; r++)
        #pragma unroll
        for (int n = 0; n < NB; n++)
            wc[r][n] = *(const float4*)&wcs[n * DVAL + r * 128 + lane * 4];

    const int gw = blockIdx.x * 8 + warp;
    const int nw = gridDim.x * 8;

    for (int row = gw; row < NROWS; row += nw) {
        const float4* er = (const float4*)(e + (size_t)row * DVAL);

        float4 ev[4];
        #pragma unroll
        for (int r = 0; r < 4; r++) ev[r] = er[r * 32 + lane];

        float acc[NB];
        #pragma unroll
        for (int n = 0; n < NB; n++) acc[n] = 0.f;

        #pragma unroll
        for (int r = 0; r < 4; r++) {
            #pragma unroll
            for (int n = 0; n < NB; n++) {
                acc[n] += ev[r].x * wc[r][n].x;
                acc[n] += ev[r].y * wc[r][n].y;
                acc[n] += ev[r].z * wc[r][n].z;
                acc[n] += ev[r].w * wc[r][n].w;
            }
        }

        #pragma unroll
        for (int n = 0; n < NB; n++) {
            #pragma unroll
            for (int off = 16; off > 0; off >>= 1)
                acc[n] += __shfl_xor_sync(0xFFFFFFFFu, acc[n], off);
        }

        if (lane == 0) {
            float* tp = &g_t[row * NB];
            #pragma unroll
            for (int n = 0; n < NB; n++) tp[n] = acc[n];
        }
    }
}

// ---------------------------------------------------------------------------
// Kernel 2: out[b,a,n] + broadcast over j.
// grid = (16 a-tiles, 8 b) = 128 blocks, block = 1024 threads (32 warps).
// Warp w: a_local = w>>3, s-chunk q = w&7 (256 s each) -> 8 iters/lane.
// 32 warps/SM hides LDS/L2 latency; cross-warp combine via smem partials.
// ---------------------------------------------------------------------------
__global__ __launch_bounds__(1024) void out_kernel(const float* __restrict__ W_ll,
                                                   const float* __restrict__ b_ll,
                                                   const float* __restrict__ b_fl,
                                                   float* __restrict__ out) {
    __shared__ float ts[MSP * NB];        // 40 KB
    __shared__ float partial[32 * NB];    // 640 B
    __shared__ float finalv[4 * NB];      // 80 B
    const int b   = blockIdx.y;
    const int at  = blockIdx.x;
    const int tid = threadIdx.x;

    // Stage t[b] (40 KB) from L2 with float4 loads: 2.5 iters/thread
    {
        const float4* src = (const float4*)&g_t[b * (MSP * NB)];
        float4* dst = (float4*)ts;
        for (int i = tid; i < (MSP * NB) / 4; i += 1024) dst[i] = src[i];
    }
    __syncthreads();

    const int lane    = tid & 31;
    const int w       = tid >> 5;
    const int a_local = w >> 3;           // 0..3
    const int q       = w & 7;            // 0..7  s-chunk
    const int a       = at * 4 + a_local;
    const float* wrow = W_ll + (size_t)a * MSP + q * 256;
    const float* tsp  = ts + (q * 256) * NB;

    // Front-batch the 8 W_ll loads (independent, coalesced, L2-resident)
    float wv[8];
    #pragma unroll
    for (int k = 0; k < 8; k++) wv[k] = wrow[lane + 32 * k];

    float a0 = 0.f, a1 = 0.f, a2 = 0.f, a3 = 0.f, a4 = 0.f;
    #pragma unroll
    for (int k = 0; k < 8; k++) {
        const float* tp = &tsp[(lane + 32 * k) * NB];   // stride-5: conflict-free
        a0 += wv[k] * tp[0];
        a1 += wv[k] * tp[1];
        a2 += wv[k] * tp[2];
        a3 += wv[k] * tp[3];
        a4 += wv[k] * tp[4];
    }
    #pragma unroll
    for (int off = 16; off > 0; off >>= 1) {
        a0 += __shfl_xor_sync(0xFFFFFFFFu, a0, off);
        a1 += __shfl_xor_sync(0xFFFFFFFFu, a1, off);
        a2 += __shfl_xor_sync(0xFFFFFFFFu, a2, off);
        a3 += __shfl_xor_sync(0xFFFFFFFFu, a3, off);
        a4 += __shfl_xor_sync(0xFFFFFFFFu, a4, off);
    }
    if (lane == 0) {
        float* pp = &partial[w * NB];
        pp[0] = a0; pp[1] = a1; pp[2] = a2; pp[3] = a3; pp[4] = a4;
    }
    __syncthreads();

    // 20 threads finalize: sum 8 chunks + bias terms
    if (tid < 4 * NB) {
        int al = tid / NB, n = tid - al * NB;
        float s = 0.f;
        #pragma unroll
        for (int qq = 0; qq < 8; qq++) s += partial[(al * 8 + qq) * NB + n];
        finalv[tid] = s + b_ll[at * 4 + al] * g_S[n] + b_fl[n];
    }
    __syncthreads();

    // Broadcast write: 4 a's x 64 j x 5 n = 1280 contiguous floats
    float* base = out + ((size_t)(b * AVAL + at * 4)) * (AVAL * NB);
    for (int idx = tid; idx < 4 * AVAL * NB; idx += 1024) {
        int al = idx / (AVAL * NB);
        int n  = idx % NB;
        base[idx] = finalv[al * NB + n];
    }
}

// ---------------------------------------------------------------------------
extern "C" void kernel_launch(void* const* d_in, const int* in_sizes, int n_in,
                              void* d_out, int out_size) {
    const float* e    = (const float*)d_in[0];
    const float* W_ll = (const float*)d_in[1];
    const float* b_ll = (const float*)d_in[2];
    const float* W_fl = (const float*)d_in[3];
    const float* b_fl = (const float*)d_in[4];
    float* out = (float*)d_out;

    t_kernel<<<296, 256>>>(e, W_fl);
    out_kernel<<<dim3(16, BVAL), 1024>>>(W_ll, b_ll, b_fl, out);
}